// round 14
// baseline (speedup 1.0000x reference)
#include <cuda_runtime.h>
#include <cstdint>
#include <math.h>

// ---------------------------------------------------------------------------
// GAT layer (B=4, N=4096, D=256) — legacy tf32 mma, occ-2, ILP-pipelined
//   wa1=W@a1, wa2=W@a2; Ax=feat@wa1, Ay=feat@wa2 (fp32 exact)
//   h = feat@W   (tf32x3 tensor GEMM, ~fp32 accurate, stored tf32)
//   P[i,j] = adj ? (Ax[j]+Ay[i]>0 ? e^Ax[j]e^Ay[i] : e^{.2Ax[j]}e^{.2Ay[i]}) : 0
//   out = ELU( (P @ h) / rowsum(P) )   (tf32 mma, fused epilogue)
// ---------------------------------------------------------------------------

#define ALPHA  0.2f
#define NB     4
#define NN     4096
#define DDIM   256
#define IT     64
#define JT     32
#define NCHUNK (NN / JT)
#define MT     256
#define FSTR   264
#define PSTR   36

// h-gemm smem layout (float offsets)
#define H_AH 0
#define H_AL 4608
#define H_BH 9216
#define H_BL 17664
#define H_SMEM_BYTES (26112 * 4)

// main kernel smem layout (BYTE offsets)
#define FBO   0
#define FBSZ  33792
#define PBO   67584
#define PBSZ  9216
#define T4O   86016
#define RSO   87168
#define MAIN_SMEM_BYTES 87424

// ---------------- device scratch -------------------------------------------
__device__ float  g_h[(size_t)NB * NN * DDIM];
__device__ float4 g_t4[NB * NN];                // (Ax, e^Ax, e^.2Ax, 0)
__device__ float  g_wa1[DDIM], g_wa2[DDIM];
__device__ float  g_Ay[NB * NN], g_eyi[NB * NN], g_eyi5[NB * NN];

// ---------------- helpers ---------------------------------------------------
__device__ __forceinline__ float tf32r(float x) {
    unsigned int u;
    asm("cvt.rna.tf32.f32 %0, %1;" : "=r"(u) : "f"(x));
    return __uint_as_float(u);
}
__device__ __forceinline__ uint32_t s2u(const void* p) {
    uint32_t a;
    asm("{ .reg .u64 t; cvta.to.shared.u64 t, %1; cvt.u32.u64 %0, t; }"
        : "=r"(a) : "l"(p));
    return a;
}
__device__ __forceinline__ void cpa16(uint32_t dst, const void* src) {
    asm volatile("cp.async.cg.shared.global [%0], [%1], 16;"
                 :: "r"(dst), "l"(src) : "memory");
}
#define CPACOMMIT() asm volatile("cp.async.commit_group;" ::: "memory")
#define CPAWAIT0()  asm volatile("cp.async.wait_group 0;" ::: "memory")
__device__ __forceinline__ void mma8(float* c,
        unsigned int a0, unsigned int a1, unsigned int a2, unsigned int a3,
        unsigned int b0, unsigned int b1) {
    asm volatile(
      "mma.sync.aligned.m16n8k8.row.col.f32.tf32.tf32.f32 "
      "{%0,%1,%2,%3}, {%4,%5,%6,%7}, {%8,%9}, {%0,%1,%2,%3};\n"
      : "+f"(c[0]), "+f"(c[1]), "+f"(c[2]), "+f"(c[3])
      : "r"(a0), "r"(a1), "r"(a2), "r"(a3), "r"(b0), "r"(b1));
}
__device__ __forceinline__ float elu(float v) {
    return (v > 0.f) ? v : (expf(v) - 1.0f);
}

// ---------------- K1: wa1 = W@a1, wa2 = W@a2 --------------------------------
__global__ void prep_w_kernel(const float* __restrict__ W,
                              const float* __restrict__ a1,
                              const float* __restrict__ a2) {
    int r = blockIdx.x, j = threadIdx.x;
    float w  = W[r * DDIM + j];
    float p1 = w * a1[j], p2 = w * a2[j];
    #pragma unroll
    for (int o = 16; o; o >>= 1) {
        p1 += __shfl_xor_sync(0xffffffffu, p1, o);
        p2 += __shfl_xor_sync(0xffffffffu, p2, o);
    }
    __shared__ float s1[8], s2[8];
    if ((j & 31) == 0) { s1[j >> 5] = p1; s2[j >> 5] = p2; }
    __syncthreads();
    if (j == 0) {
        float t1 = 0.f, t2 = 0.f;
        #pragma unroll
        for (int k = 0; k < 8; k++) { t1 += s1[k]; t2 += s2[k]; }
        g_wa1[r] = t1; g_wa2[r] = t2;
    }
}

// ---------------- K2: Ax/Ay dots + fused exp table --------------------------
__global__ void prep_nodes_kernel(const float* __restrict__ feat) {
    __shared__ float w1s[DDIM], w2s[DDIM];
    int tid = threadIdx.x;
    if (tid < DDIM) { w1s[tid] = g_wa1[tid]; w2s[tid] = g_wa2[tid]; }
    __syncthreads();
    int row = blockIdx.x * 8 + (tid >> 5), ln = tid & 31;
    size_t base = ((size_t)row << 8) + ln * 8;
    float4 v0 = *(const float4*)(feat + base);
    float4 v1 = *(const float4*)(feat + base + 4);
    const float* w1 = w1s + ln * 8;
    const float* w2 = w2s + ln * 8;
    float s1 = v0.x*w1[0]+v0.y*w1[1]+v0.z*w1[2]+v0.w*w1[3]
             + v1.x*w1[4]+v1.y*w1[5]+v1.z*w1[6]+v1.w*w1[7];
    float s2 = v0.x*w2[0]+v0.y*w2[1]+v0.z*w2[2]+v0.w*w2[3]
             + v1.x*w2[4]+v1.y*w2[5]+v1.z*w2[6]+v1.w*w2[7];
    #pragma unroll
    for (int o = 16; o; o >>= 1) {
        s1 += __shfl_xor_sync(0xffffffffu, s1, o);
        s2 += __shfl_xor_sync(0xffffffffu, s2, o);
    }
    if (ln == 0) {
        g_t4[row] = make_float4(s1, expf(s1), expf(ALPHA * s1), 0.f);
        g_Ay[row] = s2; g_eyi[row] = expf(s2); g_eyi5[row] = expf(ALPHA * s2);
    }
}

// ---------------- K3: h = feat@W  (tf32x3, proven) --------------------------
__global__ __launch_bounds__(512, 1)
void h_gemm_kernel(const float* __restrict__ feat, const float* __restrict__ W) {
    extern __shared__ float sm[];
    int tid = threadIdx.x, wrp = tid >> 5, lane = tid & 31;
    int R0 = blockIdx.x * 128;
    int g = lane >> 2, tg = lane & 3;
    int mw = (wrp & 1) * 64, nb = (wrp >> 1) * 32;
    int r = tid >> 2, cg = tid & 3;

    float acc[4][4][4];
    #pragma unroll
    for (int mt = 0; mt < 4; mt++)
        #pragma unroll
        for (int nt = 0; nt < 4; nt++)
            #pragma unroll
            for (int q = 0; q < 4; q++) acc[mt][nt][q] = 0.f;

    for (int c = 0; c < 8; c++) {
        int k0 = c * JT;
        __syncthreads();
        {   // stage A (feat rows, hi/lo)
            size_t s = (((size_t)(R0 + r)) << 8) + k0 + cg * 8;
            float4 v0 = *(const float4*)(feat + s);
            float4 v1 = *(const float4*)(feat + s + 4);
            float* ah = sm + H_AH + r * PSTR + cg * 8;
            float* al = sm + H_AL + r * PSTR + cg * 8;
            float hv[8], lv[8];
            #pragma unroll
            for (int q = 0; q < 8; q++) {
                float v = (q < 4) ? ((const float*)&v0)[q] : ((const float*)&v1)[q - 4];
                hv[q] = tf32r(v); lv[q] = tf32r(v - hv[q]);
            }
            *(float4*)(ah)     = make_float4(hv[0], hv[1], hv[2], hv[3]);
            *(float4*)(ah + 4) = make_float4(hv[4], hv[5], hv[6], hv[7]);
            *(float4*)(al)     = make_float4(lv[0], lv[1], lv[2], lv[3]);
            *(float4*)(al + 4) = make_float4(lv[4], lv[5], lv[6], lv[7]);
        }
        {   // stage B (W chunk, hi/lo)
            #pragma unroll
            for (int k = 0; k < 4; k++) {
                int f = tid + k * 512, rowk = f >> 6, col = (f & 63) << 2;
                float4 v = *(const float4*)(W + (size_t)(k0 + rowk) * DDIM + col);
                float4 h, l;
                h.x = tf32r(v.x); l.x = tf32r(v.x - h.x);
                h.y = tf32r(v.y); l.y = tf32r(v.y - h.y);
                h.z = tf32r(v.z); l.z = tf32r(v.z - h.z);
                h.w = tf32r(v.w); l.w = tf32r(v.w - h.w);
                *(float4*)(sm + H_BH + rowk * FSTR + col) = h;
                *(float4*)(sm + H_BL + rowk * FSTR + col) = l;
            }
        }
        __syncthreads();
        #pragma unroll
        for (int ks = 0; ks < 4; ks++) {
            unsigned int BH0[4], BH1[4], BL0[4], BL1[4];
            const unsigned int* bh = (const unsigned int*)
                (sm + H_BH + (ks * 8 + tg) * FSTR + nb + g);
            const unsigned int* bl = (const unsigned int*)
                (sm + H_BL + (ks * 8 + tg) * FSTR + nb + g);
            #pragma unroll
            for (int nt = 0; nt < 4; nt++) {
                BH0[nt] = bh[nt * 8]; BH1[nt] = bh[nt * 8 + 4 * FSTR];
                BL0[nt] = bl[nt * 8]; BL1[nt] = bl[nt * 8 + 4 * FSTR];
            }
            #pragma unroll
            for (int mt = 0; mt < 4; mt++) {
                const unsigned int* pah = (const unsigned int*)
                    (sm + H_AH + (mw + mt * 16 + g) * PSTR + ks * 8 + tg);
                const unsigned int* pal = (const unsigned int*)
                    (sm + H_AL + (mw + mt * 16 + g) * PSTR + ks * 8 + tg);
                unsigned int ah0 = pah[0], ah1 = pah[8 * PSTR];
                unsigned int ah2 = pah[4], ah3 = pah[8 * PSTR + 4];
                unsigned int al0 = pal[0], al1 = pal[8 * PSTR];
                unsigned int al2 = pal[4], al3 = pal[8 * PSTR + 4];
                #pragma unroll
                for (int nt = 0; nt < 4; nt++) {
                    mma8(acc[mt][nt], ah0, ah1, ah2, ah3, BH0[nt], BH1[nt]);
                    mma8(acc[mt][nt], ah0, ah1, ah2, ah3, BL0[nt], BL1[nt]);
                    mma8(acc[mt][nt], al0, al1, al2, al3, BH0[nt], BH1[nt]);
                }
            }
        }
    }
    #pragma unroll
    for (int mt = 0; mt < 4; mt++) {
        float* o0 = g_h + (size_t)(R0 + mw + mt * 16 + g) * DDIM;
        float* o1 = o0 + 8 * DDIM;
        #pragma unroll
        for (int nt = 0; nt < 4; nt++) {
            int col = nb + nt * 8 + tg * 2;
            *(float2*)(o0 + col) = make_float2(tf32r(acc[mt][nt][0]),
                                               tf32r(acc[mt][nt][1]));
            *(float2*)(o1 + col) = make_float2(tf32r(acc[mt][nt][2]),
                                               tf32r(acc[mt][nt][3]));
        }
    }
}

// ---------------- K4: main kernel — occ 2, hoisted GENP, pipelined frags ----
__global__ __launch_bounds__(MT, 2)
void gat_main_kernel(const int* __restrict__ adj, float* __restrict__ out) {
    extern __shared__ float sm[];
    char* smc = (char*)sm;
    uint32_t sb = s2u(sm);
    int tid  = threadIdx.x;
    int b    = blockIdx.x >> 6;
    int i0   = (blockIdx.x & 63) * IT;
    int wrp  = tid >> 5, lane = tid & 31;
    int g = lane >> 2, tg = lane & 3;
    int mw = (wrp & 1) * 32, nb = (wrp >> 1) * 64;
    int r = tid >> 2, cg = tid & 3;

    float rAy = g_Ay  [b * NN + i0 + r];
    float rey = g_eyi [b * NN + i0 + r];
    float re5 = g_eyi5[b * NN + i0 + r];
    const int*    adjrow = adj + (((size_t)(b * NN + i0 + r)) << 12) + cg * 8;
    const float*  hbase  = g_h  + ((size_t)b << 20);
    const float4* t4g    = g_t4 + b * NN;

    float acc[2][8][4];
    #pragma unroll
    for (int mt = 0; mt < 2; mt++)
        #pragma unroll
        for (int nt = 0; nt < 8; nt++)
            #pragma unroll
            for (int q = 0; q < 4; q++) acc[mt][nt][q] = 0.f;
    float rsum = 0.f;
    int4 ar0, ar1;

#define STAGE_H(c, buf) do {                                                   \
        const float* hsrc_ = hbase + (size_t)(c) * JT * DDIM;                  \
        uint32_t fb_ = sb + FBO + (buf) * FBSZ;                                \
        _Pragma("unroll")                                                      \
        for (int k = 0; k < 8; k++) {                                          \
            int f_ = tid + k * MT;                                             \
            cpa16(fb_ + (f_ >> 6) * (FSTR * 4) + ((f_ & 63) << 4),             \
                  hsrc_ + ((f_ >> 6) << 8) + ((f_ & 63) << 2));                \
        }                                                                      \
    } while (0)

#define STAGE_T4(c, slot) do {                                                 \
        if (tid < 32) {                                                        \
            cpa16(sb + T4O + (slot) * 576 +                                    \
                      (((tid >> 3) * 9 + (tid & 7)) << 4),                     \
                  t4g + (c) * JT + tid);                                       \
        }                                                                      \
    } while (0)

#define GENP(c, buf, slot) do {                                                \
        const float4* t4s_ = (const float4*)(smc + T4O + (slot) * 576);        \
        float pq_[8];                                                          \
        _Pragma("unroll")                                                      \
        for (int q = 0; q < 8; q++) {                                          \
            int av_ = (q < 4) ? ((const int*)&ar0)[q]                          \
                              : ((const int*)&ar1)[q - 4];                     \
            float4 t_ = t4s_[cg * 9 + q];                                      \
            float lg_ = t_.x + rAy;                                            \
            float e_  = (lg_ > 0.f) ? t_.y * rey : t_.z * re5;                 \
            float p_  = (av_ > 0) ? tf32r(e_) : 0.f;                           \
            pq_[q] = p_; rsum += p_;                                           \
        }                                                                      \
        float* pb_ = (float*)(smc + PBO + (buf) * PBSZ) + r * PSTR + cg * 8;   \
        *(float4*)(pb_)     = make_float4(pq_[0], pq_[1], pq_[2], pq_[3]);     \
        *(float4*)(pb_ + 4) = make_float4(pq_[4], pq_[5], pq_[6], pq_[7]);     \
    } while (0)

#define LOADB(d0, d1, ks_) do {                                                \
        const unsigned int* pbb_ = (const unsigned int*)                       \
            (fbF_ + ((ks_) * 8 + tg) * FSTR + nb + g);                         \
        _Pragma("unroll")                                                      \
        for (int nt = 0; nt < 8; nt++) {                                       \
            (d0)[nt] = pbb_[nt * 8];                                           \
            (d1)[nt] = pbb_[nt * 8 + 4 * FSTR];                                \
        }                                                                      \
    } while (0)

#define MMACHUNK(buf) do {                                                     \
        const float* pbF_ = (const float*)(smc + PBO + (buf) * PBSZ);          \
        const float* fbF_ = (const float*)(smc + FBO + (buf) * FBSZ);          \
        unsigned int Bb0[2][8], Bb1[2][8];                                     \
        LOADB(Bb0[0], Bb1[0], 0);                                              \
        _Pragma("unroll")                                                      \
        for (int ks = 0; ks < 4; ks++) {                                       \
            if (ks < 3)                                                        \
                LOADB(Bb0[(ks + 1) & 1], Bb1[(ks + 1) & 1], ks + 1);           \
            _Pragma("unroll")                                                  \
            for (int mt = 0; mt < 2; mt++) {                                   \
                const unsigned int* pa_ = (const unsigned int*)                \
                    (pbF_ + (mw + mt * 16 + g) * PSTR + ks * 8 + tg);          \
                unsigned int a0_ = pa_[0], a1_ = pa_[8 * PSTR];                \
                unsigned int a2_ = pa_[4], a3_ = pa_[8 * PSTR + 4];            \
                _Pragma("unroll")                                              \
                for (int nt = 0; nt < 8; nt++)                                 \
                    mma8(acc[mt][nt], a0_, a1_, a2_, a3_,                      \
                         Bb0[ks & 1][nt], Bb1[ks & 1][nt]);                    \
            }                                                                  \
        }                                                                      \
    } while (0)

    // ---- prologue: stage chunk 0; P(0); prefetch adj(1) ----
    STAGE_H(0, 0);
    STAGE_T4(0, 0);
    STAGE_T4(1, 1);
    CPACOMMIT();
    ar0 = *(const int4*)(adjrow);
    ar1 = *(const int4*)(adjrow + 4);
    CPAWAIT0();
    __syncthreads();
    GENP(0, 0, 0);
    ar0 = *(const int4*)(adjrow + JT);
    ar1 = *(const int4*)(adjrow + JT + 4);
    __syncthreads();

    // ---- mainloop: GENP hoisted before MMA; adj fetched under MMA ----
    for (int c = 0; c < NCHUNK; c++) {
        int buf = c & 1;
        if (c + 1 < NCHUNK) STAGE_H(c + 1, buf ^ 1);
        if (c + 2 < NCHUNK) STAGE_T4(c + 2, c & 1);
        CPACOMMIT();
        if (c + 1 < NCHUNK) GENP(c + 1, buf ^ 1, (c + 1) & 1);
        if (c + 2 < NCHUNK) {
            int j0n = (c + 2) * JT;
            ar0 = *(const int4*)(adjrow + j0n);
            ar1 = *(const int4*)(adjrow + j0n + 4);
        }
        MMACHUNK(buf);
        CPAWAIT0();
        __syncthreads();
    }
#undef STAGE_H
#undef STAGE_T4
#undef GENP
#undef LOADB
#undef MMACHUNK

    // ---- rowsum reduce (4 adjacent lanes per row) ----
    rsum += __shfl_xor_sync(0xffffffffu, rsum, 1);
    rsum += __shfl_xor_sync(0xffffffffu, rsum, 2);
    float* rs = (float*)(smc + RSO);
    if (cg == 0) rs[r] = 1.0f / rsum;
    __syncthreads();

    // ---- fused epilogue: scale + ELU + store ----
    #pragma unroll
    for (int mt = 0; mt < 2; mt++) {
        int rloc = mw + mt * 16 + g;
        float inv0 = rs[rloc];
        float inv1 = rs[rloc + 8];
        float* o0 = out + (size_t)(b * NN + i0 + rloc) * DDIM;
        float* o1 = o0 + 8 * DDIM;
        #pragma unroll
        for (int nt = 0; nt < 8; nt++) {
            int col = nb + nt * 8 + tg * 2;
            *(float2*)(o0 + col) = make_float2(elu(acc[mt][nt][0] * inv0),
                                               elu(acc[mt][nt][1] * inv0));
            *(float2*)(o1 + col) = make_float2(elu(acc[mt][nt][2] * inv1),
                                               elu(acc[mt][nt][3] * inv1));
        }
    }
}

// ---------------------------------------------------------------------------
extern "C" void kernel_launch(void* const* d_in, const int* in_sizes, int n_in,
                              void* d_out, int out_size) {
    const float* feat = (const float*)d_in[0];
    const int*   adj  = (const int*)d_in[1];
    const float* W    = (const float*)d_in[2];
    const float* a1   = (const float*)d_in[3];
    const float* a2   = (const float*)d_in[4];
    float* out = (float*)d_out;

    cudaFuncSetAttribute(h_gemm_kernel,
                         cudaFuncAttributeMaxDynamicSharedMemorySize,
                         H_SMEM_BYTES);
    cudaFuncSetAttribute(gat_main_kernel,
                         cudaFuncAttributeMaxDynamicSharedMemorySize,
                         MAIN_SMEM_BYTES);

    prep_w_kernel    <<<256, 256>>>(W, a1, a2);
    prep_nodes_kernel<<<2048, 256>>>(feat);
    h_gemm_kernel    <<<(NB * NN) / 128, 512, H_SMEM_BYTES>>>(feat, W);
    gat_main_kernel  <<<NB * (NN / IT), MT, MAIN_SMEM_BYTES>>>(adj, out);
    (void)in_sizes; (void)n_in; (void)out_size;
}